// round 1
// baseline (speedup 1.0000x reference)
#include <cuda_runtime.h>
#include <cstdint>

// Problem constants (fixed by the reference)
#define DD    256          // embedding dim
#define KK    8192         // num embeddings
#define NTOK  16384        // 16 * 32 * 32 tokens
#define HWSZ  1024         // 32*32
#define QSIZE 4194304      // 16*256*32*32  (quantized_out elements)
// Output layout assumption: [quantized_out (QSIZE) | loss (1) | indices (NTOK)] as float32

// Scratch (static device globals: allocation-free per harness rules)
__device__ float g_embT[DD * KK];   // emb transposed: [d][k], 8 MB
__device__ float g_c[KK];           // ||e_k||^2
__device__ float g_loss;            // sum of (q - z)^2

// ---------------------------------------------------------------------------
// Prep 1: transpose emb [K][D] -> g_embT [D][K]; also zero the loss accumulator
// ---------------------------------------------------------------------------
__global__ void prep_transpose(const float* __restrict__ emb) {
    __shared__ float tile[32][33];
    int k0 = blockIdx.x * 32, d0 = blockIdx.y * 32;
    int tx = threadIdx.x, ty = threadIdx.y;   // 32 x 8
    if (blockIdx.x == 0 && blockIdx.y == 0 && tx == 0 && ty == 0) g_loss = 0.f;
#pragma unroll
    for (int r = 0; r < 32; r += 8)
        tile[ty + r][tx] = emb[(size_t)(k0 + ty + r) * DD + d0 + tx];
    __syncthreads();
#pragma unroll
    for (int r = 0; r < 32; r += 8)
        g_embT[(size_t)(d0 + ty + r) * KK + k0 + tx] = tile[tx][ty + r];
}

// ---------------------------------------------------------------------------
// Prep 2: c_k = ||e_k||^2   (one warp per code)
// ---------------------------------------------------------------------------
__global__ void comp_c(const float* __restrict__ emb) {
    int k    = blockIdx.x * 8 + (threadIdx.x >> 5);
    int lane = threadIdx.x & 31;
    const float* row = emb + (size_t)k * DD;
    float s = 0.f;
#pragma unroll
    for (int d = lane; d < DD; d += 32) { float v = row[d]; s += v * v; }
#pragma unroll
    for (int o = 16; o > 0; o >>= 1) s += __shfl_xor_sync(0xffffffffu, s, o);
    if (lane == 0) g_c[k] = s;
}

// ---------------------------------------------------------------------------
// Main fused kernel: per 128-token tile, loop over all 64 code tiles of 128,
// fp32 SGEMM (128x128x16, 8x8 micro-tile) -> key = c_k - 2*s -> packed argmin.
// Then gather emb[idx], write quantized (BCHW), indices, and loss partial.
// ---------------------------------------------------------------------------
__global__ void __launch_bounds__(256, 1) vq_main(const float* __restrict__ x,
                                                  const float* __restrict__ emb,
                                                  float* __restrict__ out) {
    __shared__ float As[2][16][128];
    __shared__ float Bs[2][16][128];
    __shared__ unsigned long long best[128];
    __shared__ int idx_s[128];

    const int tid = threadIdx.x;
    const int tx  = tid & 15;           // code group
    const int ty  = tid >> 4;           // token group
    const int m0  = blockIdx.x * 128;   // first token of this CTA
    const int b   = m0 >> 10;           // batch index (128 | 1024, tile stays in one batch)
    const int hw0 = m0 & 1023;
    // x is BCHW: x[b][d][hw] -> A[d][t] = Ag[d*1024 + t], already token-contiguous.
    const float* Ag = x + ((size_t)b * DD) * HWSZ + hw0;

    if (tid < 128) best[tid] = ~0ULL;

    const int lrow = tid >> 5;          // 0..7   (staging row)
    const int lcol = (tid & 31) * 4;    // 0..124 (staging col, float4)

    for (int ct = 0; ct < KK / 128; ++ct) {
        const float* Bg = g_embT + ct * 128;   // B[d][k] = Bg[d*KK + k]

        // preload stage 0
        float4 pa0 = *(const float4*)(Ag + (size_t)lrow * HWSZ + lcol);
        float4 pa1 = *(const float4*)(Ag + (size_t)(lrow + 8) * HWSZ + lcol);
        float4 pb0 = *(const float4*)(Bg + (size_t)lrow * KK + lcol);
        float4 pb1 = *(const float4*)(Bg + (size_t)(lrow + 8) * KK + lcol);
        *(float4*)&As[0][lrow][lcol]     = pa0;
        *(float4*)&As[0][lrow + 8][lcol] = pa1;
        *(float4*)&Bs[0][lrow][lcol]     = pb0;
        *(float4*)&Bs[0][lrow + 8][lcol] = pb1;
        __syncthreads();

        float acc[8][8];
#pragma unroll
        for (int i = 0; i < 8; i++)
#pragma unroll
            for (int j = 0; j < 8; j++) acc[i][j] = 0.f;

#pragma unroll 1
        for (int ks = 0; ks < 16; ++ks) {
            const int cur = ks & 1;
            float4 na0, na1, nb0, nb1;
            if (ks < 15) {
                const float* An = Ag + (size_t)(ks + 1) * 16 * HWSZ;
                const float* Bn = Bg + (size_t)(ks + 1) * 16 * KK;
                na0 = *(const float4*)(An + (size_t)lrow * HWSZ + lcol);
                na1 = *(const float4*)(An + (size_t)(lrow + 8) * HWSZ + lcol);
                nb0 = *(const float4*)(Bn + (size_t)lrow * KK + lcol);
                nb1 = *(const float4*)(Bn + (size_t)(lrow + 8) * KK + lcol);
            }
#pragma unroll
            for (int kk = 0; kk < 16; ++kk) {
                float4 av0 = *(const float4*)&As[cur][kk][ty * 8];
                float4 av1 = *(const float4*)&As[cur][kk][ty * 8 + 4];
                float4 bv0 = *(const float4*)&Bs[cur][kk][tx * 8];
                float4 bv1 = *(const float4*)&Bs[cur][kk][tx * 8 + 4];
                float a[8]  = {av0.x, av0.y, av0.z, av0.w, av1.x, av1.y, av1.z, av1.w};
                float bb[8] = {bv0.x, bv0.y, bv0.z, bv0.w, bv1.x, bv1.y, bv1.z, bv1.w};
#pragma unroll
                for (int i = 0; i < 8; i++)
#pragma unroll
                    for (int j = 0; j < 8; j++) acc[i][j] += a[i] * bb[j];
            }
            if (ks < 15) {
                const int nxt = cur ^ 1;
                *(float4*)&As[nxt][lrow][lcol]     = na0;
                *(float4*)&As[nxt][lrow + 8][lcol] = na1;
                *(float4*)&Bs[nxt][lrow][lcol]     = nb0;
                *(float4*)&Bs[nxt][lrow + 8][lcol] = nb1;
                __syncthreads();
            }
        }

        // Epilogue: key = ||e||^2 - 2*s; pack (sortable-float << 32 | code_idx)
        // so atomicMin gives min key with smallest index on ties (matches argmin).
        float4 c0 = *(const float4*)(g_c + ct * 128 + tx * 8);
        float4 c1 = *(const float4*)(g_c + ct * 128 + tx * 8 + 4);
        float cc[8] = {c0.x, c0.y, c0.z, c0.w, c1.x, c1.y, c1.z, c1.w};
#pragma unroll
        for (int i = 0; i < 8; i++) {
            unsigned long long bp = ~0ULL;
#pragma unroll
            for (int j = 0; j < 8; j++) {
                float key = cc[j] - 2.f * acc[i][j];
                unsigned u = __float_as_uint(key);
                u = (u & 0x80000000u) ? ~u : (u | 0x80000000u);
                unsigned long long p =
                    ((unsigned long long)u << 32) | (unsigned)(ct * 128 + tx * 8 + j);
                bp = (p < bp) ? p : bp;
            }
            atomicMin(&best[ty * 8 + i], bp);
        }
    }

    __syncthreads();
    if (tid < 128) {
        unsigned long long p = best[tid];
        int idx = (int)(unsigned)(p & 0xFFFFFFFFULL);
        idx_s[tid] = idx;
        out[QSIZE + 1 + m0 + tid] = (float)idx;   // indices as float
    }
    __syncthreads();

    // Gather + quantized write (coalesced along tokens) + loss partial
    const int t  = tid & 127;
    const int dh = tid >> 7;                      // 0 or 1 -> d halves
    const int idx = idx_s[t];
    const float* erow = emb + (size_t)idx * DD + dh * 128;
    const float* xcol = Ag + (size_t)dh * 128 * HWSZ + t;
    float* qout = out + ((size_t)b * DD) * HWSZ + hw0 + (size_t)dh * 128 * HWSZ + t;
    float lsum = 0.f;
#pragma unroll 8
    for (int ddn = 0; ddn < 128; ++ddn) {
        float q = erow[ddn];
        float z = xcol[(size_t)ddn * HWSZ];
        float df = q - z;
        lsum += df * df;
        qout[(size_t)ddn * HWSZ] = q;
    }
#pragma unroll
    for (int o = 16; o > 0; o >>= 1) lsum += __shfl_xor_sync(0xffffffffu, lsum, o);
    if ((tid & 31) == 0) atomicAdd(&g_loss, lsum);
}

// ---------------------------------------------------------------------------
// Finalize: loss = q_latent + 0.25*e_latent = 1.25 * mean((q-z)^2)
// ---------------------------------------------------------------------------
__global__ void finalize_loss(float* __restrict__ out) {
    out[QSIZE] = 1.25f * g_loss * (1.0f / (float)QSIZE);
}

extern "C" void kernel_launch(void* const* d_in, const int* in_sizes, int n_in,
                              void* d_out, int out_size) {
    const float* x   = (const float*)d_in[0];   // [16,256,32,32] BCHW
    const float* emb = (const float*)d_in[1];   // [8192,256]
    float* out = (float*)d_out;

    prep_transpose<<<dim3(KK / 32, DD / 32), dim3(32, 8)>>>(emb);
    comp_c<<<KK / 8, 256>>>(emb);
    vq_main<<<NTOK / 128, 256>>>(x, emb, out);
    finalize_loss<<<1, 1>>>(out);
}

// round 3
// speedup vs baseline: 2.1255x; 2.1255x over previous
#include <cuda_runtime.h>
#include <cstdint>

#define DD    256
#define KK    8192
#define NTOK  16384
#define HWSZ  1024
#define QSIZE 4194304
// out layout: [quantized (QSIZE) | loss (1) | indices (NTOK)] as float32 (confirmed R1)

__device__ float g_embT[DD * KK];   // tf32-rounded emb, [d][k]
__device__ float g_c[KK];           // exact ||e_k||^2
__device__ float g_loss;

// ---------------- helpers ----------------
__device__ __forceinline__ uint32_t smem_u32(const void* p) {
    uint32_t a;
    asm("{ .reg .u64 t; cvta.to.shared.u64 t, %1; cvt.u32.u64 %0, t; }" : "=r"(a) : "l"(p));
    return a;
}
__device__ __forceinline__ void cp16(uint32_t dst, const void* src) {
    asm volatile("cp.async.cg.shared.global [%0], [%1], 16;" :: "r"(dst), "l"(src));
}
#define CP_COMMIT() asm volatile("cp.async.commit_group;")
#define CP_WAIT0()  asm volatile("cp.async.wait_group 0;")
__device__ __forceinline__ float tf32r(float x) {
    uint32_t y; asm("cvt.rna.tf32.f32 %0, %1;" : "=r"(y) : "f"(x));
    return __uint_as_float(y);
}
__device__ __forceinline__ void mma_tf32(float* d, const uint32_t* a, const uint32_t* b) {
    asm volatile(
        "mma.sync.aligned.m16n8k8.row.col.f32.tf32.tf32.f32 "
        "{%0,%1,%2,%3},{%4,%5,%6,%7},{%8,%9},{%0,%1,%2,%3};"
        : "+f"(d[0]), "+f"(d[1]), "+f"(d[2]), "+f"(d[3])
        : "r"(a[0]), "r"(a[1]), "r"(a[2]), "r"(a[3]), "r"(b[0]), "r"(b[1]));
}

// ---------------- prep: transpose + tf32-round emb; zero loss ----------------
__global__ void prep_transpose(const float* __restrict__ emb) {
    __shared__ float tile[32][33];
    int k0 = blockIdx.x * 32, d0 = blockIdx.y * 32;
    int tx = threadIdx.x, ty = threadIdx.y;   // 32 x 8
    if (blockIdx.x == 0 && blockIdx.y == 0 && tx == 0 && ty == 0) g_loss = 0.f;
#pragma unroll
    for (int r = 0; r < 32; r += 8)
        tile[ty + r][tx] = emb[(size_t)(k0 + ty + r) * DD + d0 + tx];
    __syncthreads();
#pragma unroll
    for (int r = 0; r < 32; r += 8)
        g_embT[(size_t)(d0 + ty + r) * KK + k0 + tx] = tf32r(tile[tx][ty + r]);
}

__global__ void comp_c(const float* __restrict__ emb) {
    int k    = blockIdx.x * 8 + (threadIdx.x >> 5);
    int lane = threadIdx.x & 31;
    const float* row = emb + (size_t)k * DD;
    float s = 0.f;
#pragma unroll
    for (int d = lane; d < DD; d += 32) { float v = row[d]; s += v * v; }
#pragma unroll
    for (int o = 16; o > 0; o >>= 1) s += __shfl_xor_sync(0xffffffffu, s, o);
    if (lane == 0) g_c[k] = s;
}

// ---------------- main: tf32 mma GEMM + top2 tracking + exact rescore ----------------
// smem (floats): sA 33792 | sB 8448 | sC 256 | sPack 256 (u64[128]) | sCand 2048 (u32) | sBest 128
#define SMF_A    0
#define SMF_B    33792
#define SMF_C    (33792 + 8448)
#define SMF_PACK (SMF_C + 256)
#define SMF_CAND (SMF_PACK + 256)
#define SMF_BEST (SMF_CAND + 2048)
#define SMF_TOT  (SMF_BEST + 128)          // 44928 floats = 179712 B

__global__ void __launch_bounds__(256, 1) vq_main(const float* __restrict__ x,
                                                  const float* __restrict__ emb,
                                                  float* __restrict__ out) {
    extern __shared__ float sm[];
    float*    sA    = sm + SMF_A;
    float*    sB    = sm + SMF_B;
    float*    sC    = sm + SMF_C;
    unsigned long long* sPack = (unsigned long long*)(sm + SMF_PACK);
    uint32_t* sCand = (uint32_t*)(sm + SMF_CAND);
    uint32_t* sBest = (uint32_t*)(sm + SMF_BEST);

    const int tid = threadIdx.x, lane = tid & 31, wid = tid >> 5;
    const int wr = wid >> 1, wc = wid & 1;          // warp row (4) x warp col (2)
    const int m0 = blockIdx.x * 128, b = m0 >> 10, hw0 = m0 & 1023;
    const float* Ag = x + (size_t)b * DD * HWSZ + hw0;

    const uint32_t sBaddr = smem_u32(sB);
    const uint32_t sCaddr = smem_u32(sC);

    // Load A tile (tf32-rounded) into persistent smem [256 k][132 pad]
    for (int i = tid; i < DD * 128; i += 256) {
        int d = i >> 7, m = i & 127;
        sA[d * 132 + m] = tf32r(Ag[(size_t)d * HWSZ + m]);
    }

    // Prefetch B chunk 0 (ct0, d rows 0..31) and c tile 0
    {
        const float* Bg = g_embT;   // ct=0, chunk=0
#pragma unroll
        for (int t = 0; t < 4; t++) {
            int i = tid + t * 256, r = i >> 5, c4 = i & 31;
            cp16(sBaddr + (uint32_t)(r * 132 + c4 * 4) * 4, Bg + (size_t)r * KK + c4 * 4);
        }
        if (tid < 32) cp16(sCaddr + tid * 16, g_c + tid * 4);
        CP_COMMIT();
    }

    float acc[2][8][4];
    const float INF = __int_as_float(0x7f800000);
    float m1f[4] = {INF, INF, INF, INF}, m2f[4] = {INF, INF, INF, INF};
    int   m1i[4] = {0, 0, 0, 0},        m2i[4] = {0, 0, 0, 0};

    const int ar = lane >> 2, ac = lane & 3;
    const uint32_t* Asu = (const uint32_t*)sA;

    for (int flat = 0; flat < 512; ++flat) {
        CP_WAIT0();
        __syncthreads();

        if (flat < 511) {
            int nf = flat + 1, ct = nf >> 3, ch = nf & 7;
            const float* Bg = g_embT + (size_t)(ch * 32) * KK + ct * 128;
            uint32_t dst = sBaddr + (uint32_t)(nf & 1) * 16896;
#pragma unroll
            for (int t = 0; t < 4; t++) {
                int i = tid + t * 256, r = i >> 5, c4 = i & 31;
                cp16(dst + (uint32_t)(r * 132 + c4 * 4) * 4, Bg + (size_t)r * KK + c4 * 4);
            }
            if (ch == 0 && tid < 32)
                cp16(sCaddr + (uint32_t)((ct & 1) * 128 + tid * 4) * 4, g_c + ct * 128 + tid * 4);
            CP_COMMIT();
        }

        if ((flat & 7) == 0) {
#pragma unroll
            for (int t = 0; t < 2; t++)
#pragma unroll
                for (int u = 0; u < 8; u++)
#pragma unroll
                    for (int v = 0; v < 4; v++) acc[t][u][v] = 0.f;
        }

        const uint32_t* Bsu = (const uint32_t*)(sB + (flat & 1) * 4224);
        const int kbase = (flat & 7) * 32;

#pragma unroll
        for (int ks = 0; ks < 4; ks++) {
            const int k0 = ks * 8;
            uint32_t a[2][4], bb[8][2];
#pragma unroll
            for (int t = 0; t < 2; t++) {
                int mrow = wr * 32 + t * 16 + ar;
                a[t][0] = Asu[(kbase + k0 + ac) * 132 + mrow];
                a[t][1] = Asu[(kbase + k0 + ac) * 132 + mrow + 8];
                a[t][2] = Asu[(kbase + k0 + 4 + ac) * 132 + mrow];
                a[t][3] = Asu[(kbase + k0 + 4 + ac) * 132 + mrow + 8];
            }
#pragma unroll
            for (int u = 0; u < 8; u++) {
                int ncol = wc * 64 + u * 8 + ar;
                bb[u][0] = Bsu[(k0 + ac) * 132 + ncol];
                bb[u][1] = Bsu[(k0 + 4 + ac) * 132 + ncol];
            }
#pragma unroll
            for (int t = 0; t < 2; t++)
#pragma unroll
                for (int u = 0; u < 8; u++) mma_tf32(acc[t][u], a[t], bb[u]);
        }

        if ((flat & 7) == 7) {
            // epilogue for ct = flat>>3 : keys = c - 2*s, track per-row top-2
            const int ct = flat >> 3;
            float2 ccv[8];
            const float* cbuf = sC + (ct & 1) * 128 + wc * 64 + ac * 2;
#pragma unroll
            for (int u = 0; u < 8; u++) ccv[u] = *(const float2*)(cbuf + u * 8);
            const int idx_base = ct * 128 + wc * 64 + ac * 2;
#pragma unroll
            for (int t = 0; t < 2; t++) {
#pragma unroll
                for (int h = 0; h < 2; h++) {
                    const int r = t * 2 + h;
                    float key[16];
#pragma unroll
                    for (int u = 0; u < 8; u++) {
                        key[2 * u]     = fmaf(-2.f, acc[t][u][2 * h],     ccv[u].x);
                        key[2 * u + 1] = fmaf(-2.f, acc[t][u][2 * h + 1], ccv[u].y);
                    }
                    float tmin = key[0];
#pragma unroll
                    for (int j = 1; j < 16; j++) tmin = fminf(tmin, key[j]);
                    if (tmin < m2f[r]) {
#pragma unroll
                        for (int j = 0; j < 16; j++) {
                            float kj = key[j];
                            int   id = idx_base + (j >> 1) * 8 + (j & 1);
                            if (kj < m2f[r]) {
                                if (kj < m1f[r]) {
                                    m2f[r] = m1f[r]; m2i[r] = m1i[r];
                                    m1f[r] = kj;     m1i[r] = id;
                                } else { m2f[r] = kj; m2i[r] = id; }
                            }
                        }
                    }
                }
            }
        }
    }

    // ---- candidate writeback: 8 owner threads x top2 = 16 per token ----
    __syncthreads();
#pragma unroll
    for (int t = 0; t < 2; t++)
#pragma unroll
        for (int h = 0; h < 2; h++) {
            int r = t * 2 + h;
            int row = wr * 32 + t * 16 + h * 8 + (lane >> 2);
            int slot = wc * 8 + (lane & 3) * 2;
            sCand[row * 16 + slot]     = (uint32_t)m1i[r];
            sCand[row * 16 + slot + 1] = (uint32_t)m2i[r];
        }
    if (tid < 128) sPack[tid] = ~0ULL;
    __syncthreads();

    // ---- exact fp32 rescore: thread -> (row = tid>>1, 8 cands) ----
    {
        const int row = tid >> 1, cb = (tid & 1) * 8;
        const float* zrow = Ag + row;
        int cidx[8];
        float ds[8];
#pragma unroll
        for (int c = 0; c < 8; c++) { cidx[c] = (int)sCand[row * 16 + cb + c]; ds[c] = 0.f; }
#pragma unroll 4
        for (int blk = 0; blk < 32; blk++) {
            float zb[8];
#pragma unroll
            for (int q = 0; q < 8; q++) zb[q] = zrow[(size_t)(blk * 8 + q) * HWSZ];
#pragma unroll
            for (int c = 0; c < 8; c++) {
                const float4* er = (const float4*)(emb + (size_t)cidx[c] * DD + blk * 8);
                float4 e0 = er[0], e1 = er[1];
                float s = ds[c];
                s = fmaf(e0.x, zb[0], s); s = fmaf(e0.y, zb[1], s);
                s = fmaf(e0.z, zb[2], s); s = fmaf(e0.w, zb[3], s);
                s = fmaf(e1.x, zb[4], s); s = fmaf(e1.y, zb[5], s);
                s = fmaf(e1.z, zb[6], s); s = fmaf(e1.w, zb[7], s);
                ds[c] = s;
            }
        }
        unsigned long long best = ~0ULL;
#pragma unroll
        for (int c = 0; c < 8; c++) {
            float key = g_c[cidx[c]] - 2.f * ds[c];
            unsigned u = __float_as_uint(key);
            u = (u & 0x80000000u) ? ~u : (u | 0x80000000u);
            unsigned long long p = ((unsigned long long)u << 32) | (unsigned)cidx[c];
            best = (p < best) ? p : best;
        }
        atomicMin(&sPack[row], best);
    }
    __syncthreads();
    if (tid < 128) {
        uint32_t idx = (uint32_t)(sPack[tid] & 0xFFFFFFFFULL);
        sBest[tid] = idx;
        out[QSIZE + 1 + m0 + tid] = (float)idx;
    }
    __syncthreads();

    // ---- gather + quantized write (BCHW) + loss partial ----
    {
        const int t  = tid & 127;
        const int dh = tid >> 7;
        const int idx = (int)sBest[t];
        const float* erow = emb + (size_t)idx * DD + dh * 128;
        const float* xcol = Ag + (size_t)dh * 128 * HWSZ + t;
        float* qout = out + ((size_t)b * DD) * HWSZ + hw0 + (size_t)dh * 128 * HWSZ + t;
        float lsum = 0.f;
#pragma unroll 8
        for (int ddn = 0; ddn < 128; ++ddn) {
            float q = erow[ddn];
            float z = xcol[(size_t)ddn * HWSZ];
            float df = q - z;
            lsum += df * df;
            qout[(size_t)ddn * HWSZ] = q;
        }
#pragma unroll
        for (int o = 16; o > 0; o >>= 1) lsum += __shfl_xor_sync(0xffffffffu, lsum, o);
        if ((tid & 31) == 0) atomicAdd(&g_loss, lsum);
    }
}

__global__ void finalize_loss(float* __restrict__ out) {
    out[QSIZE] = 1.25f * g_loss * (1.0f / (float)QSIZE);
}

extern "C" void kernel_launch(void* const* d_in, const int* in_sizes, int n_in,
                              void* d_out, int out_size) {
    const float* x   = (const float*)d_in[0];
    const float* emb = (const float*)d_in[1];
    float* out = (float*)d_out;

    cudaFuncSetAttribute(vq_main, cudaFuncAttributeMaxDynamicSharedMemorySize,
                         SMF_TOT * (int)sizeof(float));

    prep_transpose<<<dim3(KK / 32, DD / 32), dim3(32, 8)>>>(emb);
    comp_c<<<KK / 8, 256>>>(emb);
    vq_main<<<NTOK / 128, 256, SMF_TOT * (int)sizeof(float)>>>(x, emb, out);
    finalize_loss<<<1, 1>>>(out);
}

// round 6
// speedup vs baseline: 4.2898x; 2.0183x over previous
#include <cuda_runtime.h>
#include <cuda_fp16.h>
#include <cstdint>

#define DD    256
#define KK    8192
#define NTOK  16384
#define HWSZ  1024
#define QSIZE 4194304
// out layout: [quantized (QSIZE) | loss (1) | indices (NTOK)] fp32 (confirmed R1/R3)

__device__ __half g_embH[KK * DD];   // emb in fp16, native [k][d] layout
__device__ float  g_c[KK];           // exact ||e_k||^2
__device__ float  g_loss;

// ---- smem byte offsets ----
// A: 128 tokens x 264 halves (528B stride, +4 words/row -> conflict-free LDSM)
#define SM_A     0
#define SM_B     67584            // 2 stages x 16384B, [code][64 halves] XOR-swizzled
#define SM_C     100352           // 32KB: all ||e||^2
#define SM_PACK  133120           // u64[128]
#define SM_CAND  134144           // u32[2048]
#define SM_BEST  142336           // u32[128]
#define SMEM_BYTES 142848

// ---------------- helpers ----------------
__device__ __forceinline__ uint32_t smem_u32(const void* p) {
    uint32_t a;
    asm("{ .reg .u64 t; cvta.to.shared.u64 t, %1; cvt.u32.u64 %0, t; }" : "=r"(a) : "l"(p));
    return a;
}
__device__ __forceinline__ void cp16(uint32_t dst, const void* src) {
    asm volatile("cp.async.cg.shared.global [%0], [%1], 16;" :: "r"(dst), "l"(src));
}
#define CP_COMMIT() asm volatile("cp.async.commit_group;")
#define CP_WAIT0()  asm volatile("cp.async.wait_group 0;")
__device__ __forceinline__ void ldsm4(uint32_t& r0, uint32_t& r1, uint32_t& r2, uint32_t& r3,
                                      uint32_t addr) {
    asm volatile("ldmatrix.sync.aligned.m8n8.x4.shared.b16 {%0,%1,%2,%3}, [%4];"
                 : "=r"(r0), "=r"(r1), "=r"(r2), "=r"(r3) : "r"(addr));
}
__device__ __forceinline__ void mma16816(float* d, const uint32_t* a, const uint32_t* b) {
    asm volatile("mma.sync.aligned.m16n8k16.row.col.f32.f16.f16.f32 "
                 "{%0,%1,%2,%3},{%4,%5,%6,%7},{%8,%9},{%0,%1,%2,%3};"
                 : "+f"(d[0]), "+f"(d[1]), "+f"(d[2]), "+f"(d[3])
                 : "r"(a[0]), "r"(a[1]), "r"(a[2]), "r"(a[3]), "r"(b[0]), "r"(b[1]));
}

// ---------------- prep: emb fp32 -> fp16; zero loss ----------------
__global__ void prep_h(const float* __restrict__ emb) {
    int i = blockIdx.x * 256 + threadIdx.x;
    g_embH[i] = __float2half(emb[i]);
    if (i == 0) g_loss = 0.f;
}

__global__ void comp_c(const float* __restrict__ emb) {
    int k    = blockIdx.x * 8 + (threadIdx.x >> 5);
    int lane = threadIdx.x & 31;
    const float* row = emb + (size_t)k * DD;
    float s = 0.f;
#pragma unroll
    for (int d = lane; d < DD; d += 32) { float v = row[d]; s += v * v; }
#pragma unroll
    for (int o = 16; o > 0; o >>= 1) s += __shfl_xor_sync(0xffffffffu, s, o);
    if (lane == 0) g_c[k] = s;
}

// ---------------- main ----------------
__global__ void __launch_bounds__(256, 1) vq_main(const float* __restrict__ x,
                                                  const float* __restrict__ emb,
                                                  float* __restrict__ out) {
    extern __shared__ __align__(128) char sm[];
    const uint32_t base = smem_u32(sm);

    float*    sC    = (float*)(sm + SM_C);
    unsigned long long* sPack = (unsigned long long*)(sm + SM_PACK);
    uint32_t* sCand = (uint32_t*)(sm + SM_CAND);
    uint32_t* sBest = (uint32_t*)(sm + SM_BEST);

    const int tid = threadIdx.x, lane = tid & 31, wid = tid >> 5;
    const int wr = wid >> 1, wc = wid & 1;            // 4 warp-rows x 2 warp-cols
    const int m0 = blockIdx.x * 128, b = m0 >> 10, hw0 = m0 & 1023;
    const float* Ag = x + (size_t)b * DD * HWSZ + hw0;   // Ag[d*1024 + token]

    // ---- build A smem [token][k] fp16 (row stride 264 halves = 528B) ----
    for (int it = 0; it < 64; ++it) {
        int i  = tid + it * 256;            // 0..16383
        int dp = i >> 7, r = i & 127;       // dp = d-pair, r = token
        float v0 = Ag[(size_t)(2 * dp) * HWSZ + r];
        float v1 = Ag[(size_t)(2 * dp + 1) * HWSZ + r];
        __half2 h2 = __floats2half2_rn(v0, v1);
        *(uint32_t*)(sm + SM_A + r * 528 + dp * 4) = *(uint32_t*)&h2;
    }
    // ---- full ||e||^2 table ----
    for (int i = tid; i < KK / 4; i += 256)
        ((float4*)sC)[i] = ((const float4*)g_c)[i];

    // ---- B chunk copy (flat = ct*4+kc; 128 codes x 64 halves, swizzled) ----
    // dst(n, seg) = stage + n*128 + (seg*16 ^ (n&7)*16); src = embH[ct*128+n][kc*64 + seg*8]
    {
        // prefetch chunk 0 into stage 0
#pragma unroll
        for (int t = 0; t < 4; ++t) {
            int i = tid + t * 256, n = i >> 3, seg = i & 7;
            uint32_t dst = base + SM_B + n * 128 + ((seg * 16) ^ ((n & 7) * 16));
            cp16(dst, g_embH + (size_t)n * 256 + seg * 8);
        }
        CP_COMMIT();
    }
    __syncthreads();

    // ---- precomputed ldmatrix addresses ----
    const int i8 = lane & 7, g = lane >> 3;
    uint32_t aBase[2];
#pragma unroll
    for (int t = 0; t < 2; ++t) {
        int rowA = wr * 32 + t * 16 + (g & 1) * 8 + i8;
        aBase[t] = base + SM_A + rowA * 528 + (g >> 1) * 16;
    }
    uint32_t bBase[4], bXor[4];
    const uint32_t kadd = (g & 1) * 16;
#pragma unroll
    for (int up = 0; up < 4; ++up) {
        int n = wc * 64 + up * 16 + ((g >> 1) ? 8 : 0) + i8;
        bBase[up] = base + SM_B + n * 128;
        bXor[up]  = (uint32_t)((n & 7) * 16);
    }

    float acc[2][8][4];
    const float INF = __int_as_float(0x7f800000);
    float m1f[4] = {INF, INF, INF, INF}, m2f[4] = {INF, INF, INF, INF};
    int   m1i[4] = {0, 0, 0, 0},        m2i[4] = {0, 0, 0, 0};
    const int ac = lane & 3;

    for (int flat = 0; flat < 256; ++flat) {
        CP_WAIT0();
        __syncthreads();

        if (flat < 255) {
            int nf = flat + 1, ct = nf >> 2, kc = nf & 3;
            uint32_t stg = base + SM_B + (uint32_t)(nf & 1) * 16384;
            const __half* src0 = g_embH + (size_t)(ct * 128) * 256 + kc * 64;
#pragma unroll
            for (int t = 0; t < 4; ++t) {
                int i = tid + t * 256, n = i >> 3, seg = i & 7;
                uint32_t dst = stg + n * 128 + ((seg * 16) ^ ((n & 7) * 16));
                cp16(dst, src0 + (size_t)n * 256 + seg * 8);
            }
            CP_COMMIT();
        }

        const int ct = flat >> 2, kc = flat & 3;
        if (kc == 0) {
#pragma unroll
            for (int t = 0; t < 2; ++t)
#pragma unroll
                for (int u = 0; u < 8; ++u)
#pragma unroll
                    for (int v = 0; v < 4; ++v) acc[t][u][v] = 0.f;
        }

        const uint32_t stageOff = (uint32_t)(flat & 1) * 16384;
        const uint32_t kbA0 = (uint32_t)kc * 128;
#pragma unroll
        for (int ks = 0; ks < 4; ++ks) {
            uint32_t a[2][4], bf[8][2];
#pragma unroll
            for (int t = 0; t < 2; ++t)
                ldsm4(a[t][0], a[t][1], a[t][2], a[t][3], aBase[t] + kbA0 + ks * 32);
#pragma unroll
            for (int up = 0; up < 4; ++up) {
                uint32_t addr = bBase[up] + stageOff + (((uint32_t)ks * 32 + kadd) ^ bXor[up]);
                ldsm4(bf[2 * up][0], bf[2 * up][1], bf[2 * up + 1][0], bf[2 * up + 1][1], addr);
            }
#pragma unroll
            for (int t = 0; t < 2; ++t)
#pragma unroll
                for (int u = 0; u < 8; ++u) mma16816(acc[t][u], a[t], bf[u]);
        }

        if (kc == 3) {
            // keys = c - 2*s ; per-thread top-2 over this ct's 16 owned codes/row
            float2 ccv[8];
            const float* cbuf = sC + ct * 128 + wc * 64 + ac * 2;
#pragma unroll
            for (int u = 0; u < 8; ++u) ccv[u] = *(const float2*)(cbuf + u * 8);
            const int idx_base = ct * 128 + wc * 64 + ac * 2;
#pragma unroll
            for (int t = 0; t < 2; ++t) {
#pragma unroll
                for (int h = 0; h < 2; ++h) {
                    const int r = t * 2 + h;
                    float key[16];
#pragma unroll
                    for (int u = 0; u < 8; ++u) {
                        key[2 * u]     = fmaf(-2.f, acc[t][u][2 * h],     ccv[u].x);
                        key[2 * u + 1] = fmaf(-2.f, acc[t][u][2 * h + 1], ccv[u].y);
                    }
                    float tmin = key[0];
#pragma unroll
                    for (int j = 1; j < 16; ++j) tmin = fminf(tmin, key[j]);
                    if (tmin < m2f[r]) {
#pragma unroll
                        for (int j = 0; j < 16; ++j) {
                            float kj = key[j];
                            int   id = idx_base + (j >> 1) * 8 + (j & 1);
                            if (kj < m2f[r]) {
                                if (kj < m1f[r]) {
                                    m2f[r] = m1f[r]; m2i[r] = m1i[r];
                                    m1f[r] = kj;     m1i[r] = id;
                                } else { m2f[r] = kj; m2i[r] = id; }
                            }
                        }
                    }
                }
            }
        }
    }

    // ---- candidate writeback: 8 owner threads x top2 = 16 per token ----
    __syncthreads();
#pragma unroll
    for (int t = 0; t < 2; ++t)
#pragma unroll
        for (int h = 0; h < 2; ++h) {
            int r = t * 2 + h;
            int row = wr * 32 + t * 16 + h * 8 + (lane >> 2);
            int slot = wc * 8 + (lane & 3) * 2;
            sCand[row * 16 + slot]     = (uint32_t)m1i[r];
            sCand[row * 16 + slot + 1] = (uint32_t)m2i[r];
        }
    if (tid < 128) sPack[tid] = ~0ULL;
    __syncthreads();

    // ---- exact fp32 rescore: thread -> (row = tid>>1, 8 cands) ----
    {
        const int row = tid >> 1, cb = (tid & 1) * 8;
        const float* zrow = Ag + row;
        int cidx[8];
        float ds[8];
#pragma unroll
        for (int c = 0; c < 8; ++c) { cidx[c] = (int)sCand[row * 16 + cb + c]; ds[c] = 0.f; }
#pragma unroll 4
        for (int blk = 0; blk < 32; ++blk) {
            float zb[8];
#pragma unroll
            for (int q = 0; q < 8; ++q) zb[q] = zrow[(size_t)(blk * 8 + q) * HWSZ];
#pragma unroll
            for (int c = 0; c < 8; ++c) {
                const float4* er = (const float4*)(emb + (size_t)cidx[c] * DD + blk * 8);
                float4 e0 = er[0], e1 = er[1];
                float s = ds[c];
                s = fmaf(e0.x, zb[0], s); s = fmaf(e0.y, zb[1], s);
                s = fmaf(e0.z, zb[2], s); s = fmaf(e0.w, zb[3], s);
                s = fmaf(e1.x, zb[4], s); s = fmaf(e1.y, zb[5], s);
                s = fmaf(e1.z, zb[6], s); s = fmaf(e1.w, zb[7], s);
                ds[c] = s;
            }
        }
        unsigned long long best = ~0ULL;
#pragma unroll
        for (int c = 0; c < 8; ++c) {
            float key = g_c[cidx[c]] - 2.f * ds[c];
            unsigned u = __float_as_uint(key);
            u = (u & 0x80000000u) ? ~u : (u | 0x80000000u);
            unsigned long long p = ((unsigned long long)u << 32) | (unsigned)cidx[c];
            best = (p < best) ? p : best;
        }
        atomicMin(&sPack[row], best);
    }
    __syncthreads();
    if (tid < 128) {
        uint32_t idx = (uint32_t)(sPack[tid] & 0xFFFFFFFFULL);
        sBest[tid] = idx;
        out[QSIZE + 1 + m0 + tid] = (float)idx;
    }
    __syncthreads();

    // ---- gather + quantized write (BCHW) + loss partial ----
    {
        const int t  = tid & 127;
        const int dh = tid >> 7;
        const int idx = (int)sBest[t];
        const float* erow = emb + (size_t)idx * DD + dh * 128;
        const float* xcol = Ag + (size_t)dh * 128 * HWSZ + t;
        float* qout = out + ((size_t)b * DD) * HWSZ + hw0 + (size_t)dh * 128 * HWSZ + t;
        float lsum = 0.f;
#pragma unroll 8
        for (int dn = 0; dn < 128; ++dn) {
            float q  = erow[dn];
            float zz = xcol[(size_t)dn * HWSZ];
            float df = q - zz;
            lsum += df * df;
            qout[(size_t)dn * HWSZ] = q;
        }
#pragma unroll
        for (int o = 16; o > 0; o >>= 1) lsum += __shfl_xor_sync(0xffffffffu, lsum, o);
        if ((tid & 31) == 0) atomicAdd(&g_loss, lsum);
    }
}

__global__ void finalize_loss(float* __restrict__ out) {
    out[QSIZE] = 1.25f * g_loss * (1.0f / (float)QSIZE);
}

extern "C" void kernel_launch(void* const* d_in, const int* in_sizes, int n_in,
                              void* d_out, int out_size) {
    const float* x   = (const float*)d_in[0];
    const float* emb = (const float*)d_in[1];
    float* out = (float*)d_out;

    cudaFuncSetAttribute(vq_main, cudaFuncAttributeMaxDynamicSharedMemorySize, SMEM_BYTES);

    prep_h<<<KK * DD / 256, 256>>>(emb);
    comp_c<<<KK / 8, 256>>>(emb);
    vq_main<<<NTOK / 128, 256, SMEM_BYTES>>>(x, emb, out);
    finalize_loss<<<1, 1>>>(out);
}